// round 13
// baseline (speedup 1.0000x reference)
#include <cuda_runtime.h>
#include <cuda_fp16.h>
#include <math.h>
#include <stdint.h>

#define T_SEQ 2048
#define CDIM  1024
#define NB    2
#define NH    16
#define HD    64
#define MTOK  (NB * T_SEQ)   // 4096 token rows

// ---------------------------------------------------------------------------
// Scratch (static device globals)
// ---------------------------------------------------------------------------
__device__ __half g_x16[(size_t)MTOK * CDIM];
__device__ __half g_wq16[(size_t)CDIM * CDIM];
__device__ __half g_wk16[(size_t)CDIM * CDIM];
__device__ __half g_wv16[(size_t)CDIM * CDIM];
__device__ __half g_wo16[(size_t)CDIM * CDIM];
__device__ __half g_q16[(size_t)MTOK * CDIM];
__device__ __half g_k16[(size_t)MTOK * CDIM];
__device__ __half g_v16[(size_t)MTOK * CDIM];
__device__ __half g_a16[(size_t)MTOK * CDIM];

// ---------------------------------------------------------------------------
// Helpers
// ---------------------------------------------------------------------------
__device__ __forceinline__ uint32_t smem_u32(const void* p) {
    uint32_t a;
    asm("{ .reg .u64 t; cvta.to.shared.u64 t, %1; cvt.u32.u64 %0, t; }"
        : "=r"(a) : "l"(p));
    return a;
}
__device__ __forceinline__ float ex2f(float x) {
    float y; asm("ex2.approx.ftz.f32 %0, %1;" : "=f"(y) : "f"(x)); return y;
}
__device__ __forceinline__ void ldsm4(uint32_t& r0, uint32_t& r1,
                                      uint32_t& r2, uint32_t& r3, uint32_t addr) {
    asm volatile("ldmatrix.sync.aligned.m8n8.x4.shared.b16 {%0,%1,%2,%3}, [%4];"
                 : "=r"(r0), "=r"(r1), "=r"(r2), "=r"(r3) : "r"(addr));
}
__device__ __forceinline__ void ldsm4t(uint32_t& r0, uint32_t& r1,
                                       uint32_t& r2, uint32_t& r3, uint32_t addr) {
    asm volatile("ldmatrix.sync.aligned.m8n8.x4.trans.shared.b16 {%0,%1,%2,%3}, [%4];"
                 : "=r"(r0), "=r"(r1), "=r"(r2), "=r"(r3) : "r"(addr));
}
__device__ __forceinline__ void mma_f16(float* c, const uint32_t* a,
                                        uint32_t b0, uint32_t b1) {
    asm volatile(
        "mma.sync.aligned.m16n8k16.row.col.f32.f16.f16.f32 "
        "{%0,%1,%2,%3}, {%4,%5,%6,%7}, {%8,%9}, {%0,%1,%2,%3};"
        : "+f"(c[0]), "+f"(c[1]), "+f"(c[2]), "+f"(c[3])
        : "r"(a[0]), "r"(a[1]), "r"(a[2]), "r"(a[3]), "r"(b0), "r"(b1));
}
__device__ __forceinline__ uint32_t packh(float f0, float f1) {
    __half2 h = __floats2half2_rn(f0, f1);
    return *(uint32_t*)&h;
}

// ---------------------------------------------------------------------------
// fp32 -> fp16 converts: x (grid.y==4) and the 4 weights, one launch
// ---------------------------------------------------------------------------
__global__ __launch_bounds__(256) void cvt_all(
    const float* __restrict__ x,
    const float* __restrict__ w0, const float* __restrict__ w1,
    const float* __restrict__ w2, const float* __restrict__ w3,
    __half* __restrict__ xo,
    __half* __restrict__ o0, __half* __restrict__ o1,
    __half* __restrict__ o2, __half* __restrict__ o3, int nw4, int nx4)
{
    const float* in; __half* out; int n4;
    if (blockIdx.y == 4) { in = x;  out = xo; n4 = nx4; }
    else {
        in  = (blockIdx.y == 0) ? w0 : (blockIdx.y == 1) ? w1 :
              (blockIdx.y == 2) ? w2 : w3;
        out = (blockIdx.y == 0) ? o0 : (blockIdx.y == 1) ? o1 :
              (blockIdx.y == 2) ? o2 : o3;
        n4 = nw4;
    }
    int i = blockIdx.x * blockDim.x + threadIdx.x;
    const int stride = gridDim.x * blockDim.x;
    for (; i < n4; i += stride) {
        float4 v = *(const float4*)(in + (size_t)i * 4);
        uint2 hh; hh.x = packh(v.x, v.y); hh.y = packh(v.z, v.w);
        *(uint2*)(out + (size_t)i * 4) = hh;
    }
}

// ---------------------------------------------------------------------------
// fp16 GEMM core: CTA 128x128, 8 warps (32x64 warp tile), K-tile 64,
// 3-stage cp.async smem pipeline + EXPLICIT fragment double-buffering
// (ks+1 ldsm issued before ks MMAs). No 2-CTA reg cap: ptxas gets ~145 regs.
// ---------------------------------------------------------------------------
#define NT16  16
#define TILEB 16384       // 128 rows * 128B

__device__ __forceinline__ void stage_g2(
    uint32_t sa, uint32_t sb,
    const __half* __restrict__ A, const __half* __restrict__ B,
    int m0, int n0, int koff, int tid)
{
#pragma unroll
    for (int i = 0; i < 4; ++i) {
        int idx = tid + i * 256;
        int r = idx >> 3, c = idx & 7;
        uint32_t sw = r * 128 + ((c ^ (r & 7)) << 4);
        asm volatile("cp.async.cg.shared.global [%0], [%1], 16;"
                     :: "r"(sa + sw), "l"(A + (size_t)(m0 + r) * CDIM + koff + c * 8));
        asm volatile("cp.async.cg.shared.global [%0], [%1], 16;"
                     :: "r"(sb + sw), "l"(B + (size_t)(n0 + r) * CDIM + koff + c * 8));
    }
    asm volatile("cp.async.commit_group;" ::: "memory");
}

__device__ __forceinline__ void load_frags(
    uint32_t sAc, uint32_t sBc, int ks,
    int a_r, int a_kc, int b_r, int b_kc,
    uint32_t af[2][4], uint32_t bf[8][2])
{
#pragma unroll
    for (int mt = 0; mt < 2; ++mt) {
        const int r = a_r + mt * 16;
        uint32_t off = r * 128 + (((ks * 2 + a_kc) ^ (r & 7)) << 4);
        ldsm4(af[mt][0], af[mt][1], af[mt][2], af[mt][3], sAc + off);
    }
#pragma unroll
    for (int p = 0; p < 4; ++p) {
        const int r = b_r + p * 16;
        uint32_t off = r * 128 + (((ks * 2 + b_kc) ^ (r & 7)) << 4);
        ldsm4(bf[2 * p][0], bf[2 * p][1], bf[2 * p + 1][0], bf[2 * p + 1][1],
              sBc + off);
    }
}

__device__ __forceinline__ void gemm_core(
    uint32_t s0, const __half* A16, const __half* B16,
    int m0, int n0, int tid, int lane, int wm, int wn,
    float acc[2][8][4])
{
    uint32_t sA[3] = { s0,             s0 + 2 * TILEB, s0 + 4 * TILEB };
    uint32_t sB[3] = { s0 + TILEB,     s0 + 3 * TILEB, s0 + 5 * TILEB };

    const int a_r  = wm + (lane & 7) + ((lane >> 3) & 1) * 8;
    const int a_kc = lane >> 4;
    const int b_r  = wn + (lane & 7) + (lane >> 4) * 8;
    const int b_kc = (lane >> 3) & 1;

    stage_g2(sA[0], sB[0], A16, B16, m0, n0, 0,  tid);
    stage_g2(sA[1], sB[1], A16, B16, m0, n0, 64, tid);

    uint32_t af[2][2][4], bf[2][8][2];

    int cur = 0, nxt2 = 2;
    for (int t = 0; t < NT16; ++t) {
        if (t == NT16 - 1)
            asm volatile("cp.async.wait_group 0;" ::: "memory");
        else
            asm volatile("cp.async.wait_group 1;" ::: "memory");
        __syncthreads();
        if (t + 2 < NT16)
            stage_g2(sA[nxt2], sB[nxt2], A16, B16, m0, n0, (t + 2) * 64, tid);

        load_frags(sA[cur], sB[cur], 0, a_r, a_kc, b_r, b_kc, af[0], bf[0]);
#pragma unroll
        for (int ks = 0; ks < 4; ++ks) {
            const int pb = ks & 1, nb = pb ^ 1;
            if (ks < 3)
                load_frags(sA[cur], sB[cur], ks + 1, a_r, a_kc, b_r, b_kc,
                           af[nb], bf[nb]);
#pragma unroll
            for (int mt = 0; mt < 2; ++mt)
#pragma unroll
                for (int nt = 0; nt < 8; ++nt)
                    mma_f16(acc[mt][nt], af[pb][mt], bf[pb][nt][0], bf[pb][nt][1]);
        }
        cur  = (cur  == 2) ? 0 : cur + 1;
        nxt2 = (nxt2 == 2) ? 0 : nxt2 + 1;
    }
}

// Fused QKV projection: grid.x = 24 (8 n-blocks x {q,k,v}); fp16 out.
__global__ __launch_bounds__(256) void gemm_qkv(
    const __half* __restrict__ x16,
    const __half* __restrict__ wq16, const __half* __restrict__ wk16,
    const __half* __restrict__ wv16,
    __half* __restrict__ q16, __half* __restrict__ k16, __half* __restrict__ v16,
    const float* __restrict__ cv, const float* __restrict__ cb)
{
    extern __shared__ char gsm[];
    uint32_t s0 = smem_u32(gsm);

    const int tid = threadIdx.x, lane = tid & 31, wid = tid >> 5;
    const int wm = (wid >> 1) * 32, wn = (wid & 1) * 64;
    const int wsel = blockIdx.x >> 3;
    const int n0 = (blockIdx.x & 7) * 128;
    const int m0 = blockIdx.y * 128;

    const __half* B16 = (wsel == 0) ? wq16 : (wsel == 1) ? wk16 : wv16;
    __half* O = (wsel == 0) ? q16 : (wsel == 1) ? k16 : v16;

    float acc[2][8][4];
#pragma unroll
    for (int a = 0; a < 2; ++a)
#pragma unroll
        for (int b = 0; b < 8; ++b)
#pragma unroll
            for (int c = 0; c < 4; ++c) acc[a][b][c] = 0.0f;

    gemm_core(s0, x16, B16, m0, n0, tid, lane, wm, wn, acc);

    const int er = lane >> 2, ec = (lane & 3) * 2;
#pragma unroll
    for (int mt = 0; mt < 2; ++mt)
#pragma unroll
        for (int half = 0; half < 2; ++half) {
            const int row = m0 + wm + mt * 16 + er + half * 8;
#pragma unroll
            for (int nt = 0; nt < 8; ++nt) {
                const int col = n0 + wn + nt * 8 + ec;
                float v0 = acc[mt][nt][half * 2 + 0];
                float v1 = acc[mt][nt][half * 2 + 1];
                if (wsel == 0) {
                    const float* cvr = cv + (size_t)row * CDIM;
                    v0 += cb[col]     * cvr[col];
                    v1 += cb[col + 1] * cvr[col + 1];
                }
                *(uint32_t*)(O + (size_t)row * CDIM + col) = packh(v0, v1);
            }
        }
}

// Output projection: fp32 out + bias
__global__ __launch_bounds__(256) void gemm_out(
    const __half* __restrict__ a16, const __half* __restrict__ wo16,
    float* __restrict__ Y, const float* __restrict__ bias)
{
    extern __shared__ char gsm[];
    uint32_t s0 = smem_u32(gsm);

    const int tid = threadIdx.x, lane = tid & 31, wid = tid >> 5;
    const int wm = (wid >> 1) * 32, wn = (wid & 1) * 64;
    const int m0 = blockIdx.y * 128, n0 = blockIdx.x * 128;

    float acc[2][8][4];
#pragma unroll
    for (int a = 0; a < 2; ++a)
#pragma unroll
        for (int b = 0; b < 8; ++b)
#pragma unroll
            for (int c = 0; c < 4; ++c) acc[a][b][c] = 0.0f;

    gemm_core(s0, a16, wo16, m0, n0, tid, lane, wm, wn, acc);

    const int er = lane >> 2, ec = (lane & 3) * 2;
#pragma unroll
    for (int mt = 0; mt < 2; ++mt)
#pragma unroll
        for (int half = 0; half < 2; ++half) {
            const int row = m0 + wm + mt * 16 + er + half * 8;
            float* yrow = Y + (size_t)row * CDIM;
#pragma unroll
            for (int nt = 0; nt < 8; ++nt) {
                const int col = n0 + wn + nt * 8 + ec;
                float2 f;
                f.x = acc[mt][nt][half * 2 + 0] + bias[col];
                f.y = acc[mt][nt][half * 2 + 1] + bias[col + 1];
                *(float2*)(yrow + col) = f;
            }
        }
}

// ---------------------------------------------------------------------------
// Causal flash attention (r12 version, unchanged): 3-stage K/V pipeline,
// one barrier per k-tile. CTA: 128 q-rows; 8 warps of 16 q x 128 k.
// ---------------------------------------------------------------------------
__device__ __forceinline__ void stage_kv(
    uint32_t kvb, const __half* __restrict__ k16, const __half* __restrict__ v16,
    size_t rb, int tid)
{
#pragma unroll
    for (int i = 0; i < 4; ++i) {
        int idx = tid + i * 256;
        int r = idx >> 3, c = idx & 7;
        uint32_t sw = r * 128 + ((c ^ (r & 7)) << 4);
        size_t g = rb + (size_t)r * CDIM + c * 8;
        asm volatile("cp.async.cg.shared.global [%0], [%1], 16;" :: "r"(kvb + sw),         "l"(k16 + g));
        asm volatile("cp.async.cg.shared.global [%0], [%1], 16;" :: "r"(kvb + 16384 + sw), "l"(v16 + g));
    }
    asm volatile("cp.async.commit_group;" ::: "memory");
}

__global__ __launch_bounds__(256) void attn_mma(
    const __half* __restrict__ q16,
    const __half* __restrict__ k16, const __half* __restrict__ v16,
    __half* __restrict__ o16)
{
    extern __shared__ char asmem[];
    const uint32_t s0 = smem_u32(asmem);
    const uint32_t sQ = s0;
    const uint32_t kv0 = s0 + 16384;          // 3 buffers x 32KB: K(16K),V(16K)

    const int tid = threadIdx.x, lane = tid & 31, wid = tid >> 5;
    const int qt = (gridDim.x - 1) - blockIdx.x;   // heavy tiles first
    const int bh = blockIdx.y;
    const int b  = bh >> 4, h = bh & 15;
    const float SCL = 0.125f * 1.4426950408889634f;

    const size_t tokbase = (size_t)b * T_SEQ;
    const size_t headoff = (size_t)h * HD;
    const size_t kvbase  = tokbase * CDIM + headoff;

    {
        const __half* gq = q16 + (tokbase + qt * 128) * CDIM + headoff;
#pragma unroll
        for (int i = 0; i < 4; ++i) {
            int idx = tid + i * 256;
            int r = idx >> 3, c = idx & 7;
            uint32_t sw = r * 128 + ((c ^ (r & 7)) << 4);
            asm volatile("cp.async.cg.shared.global [%0], [%1], 16;"
                         :: "r"(sQ + sw), "l"(gq + (size_t)r * CDIM + c * 8));
        }
    }
    stage_kv(kv0, k16, v16, kvbase, tid);
    if (qt >= 1)
        stage_kv(kv0 + 32768, k16, v16, kvbase + (size_t)128 * CDIM, tid);

    uint32_t qf[4][4];
    float o[8][4];
#pragma unroll
    for (int i = 0; i < 8; ++i)
#pragma unroll
        for (int j = 0; j < 4; ++j) o[i][j] = 0.0f;
    float m_[2] = { -1e30f, -1e30f };
    float l_[2] = { 0.0f, 0.0f };

    const int b_rb = (lane & 7) + ((lane >> 4) << 3);
    const int b_kc = (lane >> 3) & 1;
    const int v_rb = (lane & 7) + (((lane >> 3) & 1) << 3);
    const int v_cs = lane >> 4;

    int cur = 0, nxt2 = 2;
    for (int kt = 0; kt <= qt; ++kt) {
        if (kt == qt)
            asm volatile("cp.async.wait_group 0;" ::: "memory");
        else
            asm volatile("cp.async.wait_group 1;" ::: "memory");
        __syncthreads();
        if (kt + 2 <= qt)
            stage_kv(kv0 + nxt2 * 32768, k16, v16,
                     kvbase + (size_t)(kt + 2) * 128 * CDIM, tid);

        if (kt == 0) {
            const int a_r  = wid * 16 + (lane & 7) + ((lane >> 3) & 1) * 8;
            const int a_kc = lane >> 4;
#pragma unroll
            for (int ks = 0; ks < 4; ++ks) {
                const int ch = ks * 2 + a_kc;
                uint32_t sw = a_r * 128 + ((ch ^ (a_r & 7)) << 4);
                ldsm4(qf[ks][0], qf[ks][1], qf[ks][2], qf[ks][3], sQ + sw);
            }
        }

        const uint32_t sK = kv0 + cur * 32768, sV = sK + 16384;

        float sc[16][4];
#pragma unroll
        for (int t = 0; t < 16; ++t)
#pragma unroll
            for (int j = 0; j < 4; ++j) sc[t][j] = 0.0f;

#pragma unroll
        for (int ks = 0; ks < 4; ++ks) {
#pragma unroll
            for (int g = 0; g < 8; ++g) {
                const int r = g * 16 + b_rb;
                const int ch = ks * 2 + b_kc;
                uint32_t sw = r * 128 + ((ch ^ (r & 7)) << 4);
                uint32_t k0, k1, k2, k3;
                ldsm4(k0, k1, k2, k3, sK + sw);
                mma_f16(sc[2 * g],     qf[ks], k0, k1);
                mma_f16(sc[2 * g + 1], qf[ks], k2, k3);
            }
        }

        const bool diag = (kt == qt);
#pragma unroll
        for (int t = 0; t < 16; ++t)
#pragma unroll
            for (int j = 0; j < 4; ++j) {
                float v = sc[t][j] * SCL;
                if (diag) {
                    const int col = t * 8 + ((lane & 3) << 1) + (j & 1);
                    const int row = (wid << 4) + (lane >> 2) + ((j >> 1) << 3);
                    if (col > row) v = -1e30f;
                }
                sc[t][j] = v;
            }

#pragma unroll
        for (int hf = 0; hf < 2; ++hf) {
            float mx = -1e30f;
#pragma unroll
            for (int t = 0; t < 16; ++t)
                mx = fmaxf(mx, fmaxf(sc[t][2 * hf], sc[t][2 * hf + 1]));
            mx = fmaxf(mx, __shfl_xor_sync(0xffffffffu, mx, 1));
            mx = fmaxf(mx, __shfl_xor_sync(0xffffffffu, mx, 2));
            const float mn = fmaxf(m_[hf], mx);
            const float corr = ex2f(m_[hf] - mn);
            float rs = 0.0f;
#pragma unroll
            for (int t = 0; t < 16; ++t) {
                float p0 = ex2f(sc[t][2 * hf]     - mn);
                float p1 = ex2f(sc[t][2 * hf + 1] - mn);
                sc[t][2 * hf] = p0; sc[t][2 * hf + 1] = p1;
                rs += p0 + p1;
            }
            rs += __shfl_xor_sync(0xffffffffu, rs, 1);
            rs += __shfl_xor_sync(0xffffffffu, rs, 2);
            l_[hf] = l_[hf] * corr + rs;
            m_[hf] = mn;
#pragma unroll
            for (int nt = 0; nt < 8; ++nt) {
                o[nt][2 * hf]     *= corr;
                o[nt][2 * hf + 1] *= corr;
            }
        }

#pragma unroll
        for (int ks2 = 0; ks2 < 8; ++ks2) {
            uint32_t ph[4];
            ph[0] = packh(sc[2 * ks2][0],     sc[2 * ks2][1]);
            ph[1] = packh(sc[2 * ks2][2],     sc[2 * ks2][3]);
            ph[2] = packh(sc[2 * ks2 + 1][0], sc[2 * ks2 + 1][1]);
            ph[3] = packh(sc[2 * ks2 + 1][2], sc[2 * ks2 + 1][3]);
#pragma unroll
            for (int ng = 0; ng < 4; ++ng) {
                const int r = ks2 * 16 + v_rb;
                const int ch = ng * 2 + v_cs;
                uint32_t sw = r * 128 + ((ch ^ (r & 7)) << 4);
                uint32_t v0, v1, v2, v3;
                ldsm4t(v0, v1, v2, v3, sV + sw);
                mma_f16(o[2 * ng],     ph, v0, v1);
                mma_f16(o[2 * ng + 1], ph, v2, v3);
            }
        }
        cur  = (cur  == 2) ? 0 : cur + 1;
        nxt2 = (nxt2 == 2) ? 0 : nxt2 + 1;
    }

#pragma unroll
    for (int hf = 0; hf < 2; ++hf) {
        const float inv = 1.0f / l_[hf];
        const int row = qt * 128 + wid * 16 + (lane >> 2) + hf * 8;
        __half* oh = o16 + (tokbase + row) * CDIM + headoff;
#pragma unroll
        for (int nt = 0; nt < 8; ++nt) {
            const int col = nt * 8 + (lane & 3) * 2;
            *(uint32_t*)(oh + col) =
                packh(o[nt][2 * hf] * inv, o[nt][2 * hf + 1] * inv);
        }
    }
}

// ---------------------------------------------------------------------------
// Launch.  Inputs: 0:x 1:mask 2:context_vector 3:w_q 4:w_k 5:w_v 6:w_o 7:b_o
//                  8:context_bias    out: f32 [2,2048,1024]
// ---------------------------------------------------------------------------
extern "C" void kernel_launch(void* const* d_in, const int* in_sizes, int n_in,
                              void* d_out, int out_size)
{
    (void)in_sizes; (void)n_in; (void)out_size;
    const float* x  = (const float*)d_in[0];
    const float* cv = (const float*)d_in[2];
    const float* wq = (const float*)d_in[3];
    const float* wk = (const float*)d_in[4];
    const float* wv = (const float*)d_in[5];
    const float* wo = (const float*)d_in[6];
    const float* bo = (const float*)d_in[7];
    const float* cb = (const float*)d_in[8];
    float* out = (float*)d_out;

    __half *x16, *wq16, *wk16, *wv16, *wo16, *q16, *k16, *v16, *a16;
    cudaGetSymbolAddress((void**)&x16,  g_x16);
    cudaGetSymbolAddress((void**)&wq16, g_wq16);
    cudaGetSymbolAddress((void**)&wk16, g_wk16);
    cudaGetSymbolAddress((void**)&wv16, g_wv16);
    cudaGetSymbolAddress((void**)&wo16, g_wo16);
    cudaGetSymbolAddress((void**)&q16,  g_q16);
    cudaGetSymbolAddress((void**)&k16,  g_k16);
    cudaGetSymbolAddress((void**)&v16,  g_v16);
    cudaGetSymbolAddress((void**)&a16,  g_a16);

    const int gemm_smem = 6 * TILEB;                 // 98304, 3-stage
    cudaFuncSetAttribute(gemm_qkv, cudaFuncAttributeMaxDynamicSharedMemorySize, gemm_smem);
    cudaFuncSetAttribute(gemm_out, cudaFuncAttributeMaxDynamicSharedMemorySize, gemm_smem);
    const int attn_smem = 16384 + 3 * 32768;         // 114688
    cudaFuncSetAttribute(attn_mma, cudaFuncAttributeMaxDynamicSharedMemorySize, attn_smem);

    const int NX4 = MTOK * CDIM / 4;
    const int NW4 = CDIM * CDIM / 4;

    cvt_all<<<dim3(512, 5), 256>>>(x, wq, wk, wv, wo,
                                   x16, wq16, wk16, wv16, wo16, NW4, NX4);

    gemm_qkv<<<dim3(24, MTOK / 128), 256, gemm_smem>>>(
        x16, wq16, wk16, wv16, q16, k16, v16, cv, cb);

    attn_mma<<<dim3(T_SEQ / 128, NB * NH), 256, attn_smem>>>(
        q16, k16, v16, a16);

    gemm_out<<<dim3(CDIM / 128, MTOK / 128), 256, gemm_smem>>>(
        a16, wo16, out, bo);
}

// round 14
// speedup vs baseline: 1.1045x; 1.1045x over previous
#include <cuda_runtime.h>
#include <cuda_fp16.h>
#include <math.h>
#include <stdint.h>

#define T_SEQ 2048
#define CDIM  1024
#define NB    2
#define NH    16
#define HD    64
#define MTOK  (NB * T_SEQ)   // 4096 token rows

// ---------------------------------------------------------------------------
// Scratch (static device globals)
// ---------------------------------------------------------------------------
__device__ __half g_x16[(size_t)MTOK * CDIM];
__device__ __half g_wq16[(size_t)CDIM * CDIM];
__device__ __half g_wk16[(size_t)CDIM * CDIM];
__device__ __half g_wv16[(size_t)CDIM * CDIM];
__device__ __half g_wo16[(size_t)CDIM * CDIM];
__device__ __half g_q16[(size_t)MTOK * CDIM];
__device__ __half g_k16[(size_t)MTOK * CDIM];
__device__ __half g_v16[(size_t)MTOK * CDIM];
__device__ __half g_a16[(size_t)MTOK * CDIM];

// ---------------------------------------------------------------------------
// Helpers
// ---------------------------------------------------------------------------
__device__ __forceinline__ uint32_t smem_u32(const void* p) {
    uint32_t a;
    asm("{ .reg .u64 t; cvta.to.shared.u64 t, %1; cvt.u32.u64 %0, t; }"
        : "=r"(a) : "l"(p));
    return a;
}
__device__ __forceinline__ float ex2f(float x) {
    float y; asm("ex2.approx.ftz.f32 %0, %1;" : "=f"(y) : "f"(x)); return y;
}
__device__ __forceinline__ void ldsm4(uint32_t& r0, uint32_t& r1,
                                      uint32_t& r2, uint32_t& r3, uint32_t addr) {
    asm volatile("ldmatrix.sync.aligned.m8n8.x4.shared.b16 {%0,%1,%2,%3}, [%4];"
                 : "=r"(r0), "=r"(r1), "=r"(r2), "=r"(r3) : "r"(addr));
}
__device__ __forceinline__ void ldsm4t(uint32_t& r0, uint32_t& r1,
                                       uint32_t& r2, uint32_t& r3, uint32_t addr) {
    asm volatile("ldmatrix.sync.aligned.m8n8.x4.trans.shared.b16 {%0,%1,%2,%3}, [%4];"
                 : "=r"(r0), "=r"(r1), "=r"(r2), "=r"(r3) : "r"(addr));
}
__device__ __forceinline__ void mma_f16(float* c, const uint32_t* a,
                                        uint32_t b0, uint32_t b1) {
    asm volatile(
        "mma.sync.aligned.m16n8k16.row.col.f32.f16.f16.f32 "
        "{%0,%1,%2,%3}, {%4,%5,%6,%7}, {%8,%9}, {%0,%1,%2,%3};"
        : "+f"(c[0]), "+f"(c[1]), "+f"(c[2]), "+f"(c[3])
        : "r"(a[0]), "r"(a[1]), "r"(a[2]), "r"(a[3]), "r"(b0), "r"(b1));
}
__device__ __forceinline__ uint32_t packh(float f0, float f1) {
    __half2 h = __floats2half2_rn(f0, f1);
    return *(uint32_t*)&h;
}

// ---------------------------------------------------------------------------
// fp32 -> fp16 converts: x (grid.y==4) and the 4 weights, one launch
// ---------------------------------------------------------------------------
__global__ __launch_bounds__(256) void cvt_all(
    const float* __restrict__ x,
    const float* __restrict__ w0, const float* __restrict__ w1,
    const float* __restrict__ w2, const float* __restrict__ w3,
    __half* __restrict__ xo,
    __half* __restrict__ o0, __half* __restrict__ o1,
    __half* __restrict__ o2, __half* __restrict__ o3, int nw4, int nx4)
{
    const float* in; __half* out; int n4;
    if (blockIdx.y == 4) { in = x;  out = xo; n4 = nx4; }
    else {
        in  = (blockIdx.y == 0) ? w0 : (blockIdx.y == 1) ? w1 :
              (blockIdx.y == 2) ? w2 : w3;
        out = (blockIdx.y == 0) ? o0 : (blockIdx.y == 1) ? o1 :
              (blockIdx.y == 2) ? o2 : o3;
        n4 = nw4;
    }
    int i = blockIdx.x * blockDim.x + threadIdx.x;
    const int stride = gridDim.x * blockDim.x;
    for (; i < n4; i += stride) {
        float4 v = *(const float4*)(in + (size_t)i * 4);
        uint2 hh; hh.x = packh(v.x, v.y); hh.y = packh(v.z, v.w);
        *(uint2*)(out + (size_t)i * 4) = hh;
    }
}

// ---------------------------------------------------------------------------
// fp16 GEMM core (round-9 exact): CTA 128x128, 8 warps (32x64 warp tile),
// K-tile 64, 2-stage double buffer (64KB smem), chunk-XOR swizzle.
// ---------------------------------------------------------------------------
#define NT16  16
#define TILEB 16384       // 128 rows * 128B

__device__ __forceinline__ void stage_g(
    uint32_t s, const __half* __restrict__ G, int r0, int koff, int tid)
{
#pragma unroll
    for (int i = 0; i < 4; ++i) {
        int idx = tid + i * 256;
        int r = idx >> 3, c = idx & 7;
        uint32_t sw = r * 128 + ((c ^ (r & 7)) << 4);
        const __half* g = G + (size_t)(r0 + r) * CDIM + koff + c * 8;
        asm volatile("cp.async.cg.shared.global [%0], [%1], 16;"
                     :: "r"(s + sw), "l"(g));
    }
}

__device__ __forceinline__ void gemm_core(
    uint32_t s0, const __half* A16, const __half* B16,
    int m0, int n0, int tid, int lane, int wm, int wn,
    float acc[2][8][4])
{
    uint32_t sA[2] = { s0,             s0 + 2 * TILEB };
    uint32_t sB[2] = { s0 + TILEB,     s0 + 3 * TILEB };

    const int a_r  = wm + (lane & 7) + ((lane >> 3) & 1) * 8;
    const int a_kc = lane >> 4;
    const int b_r  = wn + (lane & 7) + (lane >> 4) * 8;
    const int b_kc = (lane >> 3) & 1;

    stage_g(sA[0], A16, m0, 0, tid);
    stage_g(sB[0], B16, n0, 0, tid);
    asm volatile("cp.async.commit_group;" ::: "memory");

    for (int t = 0; t < NT16; ++t) {
        const int cur = t & 1, nxt = cur ^ 1;
        if (t + 1 < NT16) {
            const int ko = (t + 1) * 64;
            stage_g(sA[nxt], A16, m0, ko, tid);
            stage_g(sB[nxt], B16, n0, ko, tid);
            asm volatile("cp.async.commit_group;" ::: "memory");
            asm volatile("cp.async.wait_group 1;" ::: "memory");
        } else {
            asm volatile("cp.async.wait_group 0;" ::: "memory");
        }
        __syncthreads();

#pragma unroll
        for (int ks = 0; ks < 4; ++ks) {
            uint32_t af[2][4];
#pragma unroll
            for (int mt = 0; mt < 2; ++mt) {
                const int r = a_r + mt * 16;
                uint32_t off = r * 128 + (((ks * 2 + a_kc) ^ (r & 7)) << 4);
                ldsm4(af[mt][0], af[mt][1], af[mt][2], af[mt][3], sA[cur] + off);
            }
            uint32_t bf[8][2];
#pragma unroll
            for (int p = 0; p < 4; ++p) {
                const int r = b_r + p * 16;
                uint32_t off = r * 128 + (((ks * 2 + b_kc) ^ (r & 7)) << 4);
                ldsm4(bf[2 * p][0], bf[2 * p][1], bf[2 * p + 1][0], bf[2 * p + 1][1],
                      sB[cur] + off);
            }
#pragma unroll
            for (int mt = 0; mt < 2; ++mt)
#pragma unroll
                for (int nt = 0; nt < 8; ++nt)
                    mma_f16(acc[mt][nt], af[mt], bf[nt][0], bf[nt][1]);
        }
        __syncthreads();
    }
}

// Fused QKV projection: grid.x = 24 (8 n-blocks x {q,k,v}); fp16 out.
__global__ __launch_bounds__(256) void gemm_qkv(
    const __half* __restrict__ x16,
    const __half* __restrict__ wq16, const __half* __restrict__ wk16,
    const __half* __restrict__ wv16,
    __half* __restrict__ q16, __half* __restrict__ k16, __half* __restrict__ v16,
    const float* __restrict__ cv, const float* __restrict__ cb)
{
    extern __shared__ char gsm[];
    uint32_t s0 = smem_u32(gsm);

    const int tid = threadIdx.x, lane = tid & 31, wid = tid >> 5;
    const int wm = (wid >> 1) * 32, wn = (wid & 1) * 64;
    const int wsel = blockIdx.x >> 3;
    const int n0 = (blockIdx.x & 7) * 128;
    const int m0 = blockIdx.y * 128;

    const __half* B16 = (wsel == 0) ? wq16 : (wsel == 1) ? wk16 : wv16;
    __half* O = (wsel == 0) ? q16 : (wsel == 1) ? k16 : v16;

    float acc[2][8][4];
#pragma unroll
    for (int a = 0; a < 2; ++a)
#pragma unroll
        for (int b = 0; b < 8; ++b)
#pragma unroll
            for (int c = 0; c < 4; ++c) acc[a][b][c] = 0.0f;

    gemm_core(s0, x16, B16, m0, n0, tid, lane, wm, wn, acc);

    const int er = lane >> 2, ec = (lane & 3) * 2;
#pragma unroll
    for (int mt = 0; mt < 2; ++mt)
#pragma unroll
        for (int half = 0; half < 2; ++half) {
            const int row = m0 + wm + mt * 16 + er + half * 8;
#pragma unroll
            for (int nt = 0; nt < 8; ++nt) {
                const int col = n0 + wn + nt * 8 + ec;
                float v0 = acc[mt][nt][half * 2 + 0];
                float v1 = acc[mt][nt][half * 2 + 1];
                if (wsel == 0) {
                    const float* cvr = cv + (size_t)row * CDIM;
                    v0 += cb[col]     * cvr[col];
                    v1 += cb[col + 1] * cvr[col + 1];
                }
                *(uint32_t*)(O + (size_t)row * CDIM + col) = packh(v0, v1);
            }
        }
}

// Output projection: fp32 out + bias
__global__ __launch_bounds__(256) void gemm_out(
    const __half* __restrict__ a16, const __half* __restrict__ wo16,
    float* __restrict__ Y, const float* __restrict__ bias)
{
    extern __shared__ char gsm[];
    uint32_t s0 = smem_u32(gsm);

    const int tid = threadIdx.x, lane = tid & 31, wid = tid >> 5;
    const int wm = (wid >> 1) * 32, wn = (wid & 1) * 64;
    const int m0 = blockIdx.y * 128, n0 = blockIdx.x * 128;

    float acc[2][8][4];
#pragma unroll
    for (int a = 0; a < 2; ++a)
#pragma unroll
        for (int b = 0; b < 8; ++b)
#pragma unroll
            for (int c = 0; c < 4; ++c) acc[a][b][c] = 0.0f;

    gemm_core(s0, a16, wo16, m0, n0, tid, lane, wm, wn, acc);

    const int er = lane >> 2, ec = (lane & 3) * 2;
#pragma unroll
    for (int mt = 0; mt < 2; ++mt)
#pragma unroll
        for (int half = 0; half < 2; ++half) {
            const int row = m0 + wm + mt * 16 + er + half * 8;
            float* yrow = Y + (size_t)row * CDIM;
#pragma unroll
            for (int nt = 0; nt < 8; ++nt) {
                const int col = n0 + wn + nt * 8 + ec;
                float2 f;
                f.x = acc[mt][nt][half * 2 + 0] + bias[col];
                f.y = acc[mt][nt][half * 2 + 1] + bias[col + 1];
                *(float2*)(yrow + col) = f;
            }
        }
}

// ---------------------------------------------------------------------------
// Causal flash attention, fp16 mma, 64 q-rows per CTA (128 threads, 4 warps)
// -> 2 CTAs/SM. Per-warp tile unchanged: 16 q x 128 k. K/V double-buffered.
// ---------------------------------------------------------------------------
__device__ __forceinline__ void stage_kv128t(
    uint32_t kvb, const __half* __restrict__ k16, const __half* __restrict__ v16,
    size_t rb, int tid)
{
#pragma unroll
    for (int i = 0; i < 8; ++i) {
        int idx = tid + i * 128;          // 0..1023 -> 128 rows x 8 chunks
        int r = idx >> 3, c = idx & 7;
        uint32_t sw = r * 128 + ((c ^ (r & 7)) << 4);
        size_t g = rb + (size_t)r * CDIM + c * 8;
        asm volatile("cp.async.cg.shared.global [%0], [%1], 16;" :: "r"(kvb + sw),         "l"(k16 + g));
        asm volatile("cp.async.cg.shared.global [%0], [%1], 16;" :: "r"(kvb + 16384 + sw), "l"(v16 + g));
    }
    asm volatile("cp.async.commit_group;" ::: "memory");
}

__global__ __launch_bounds__(128) void attn_mma(
    const __half* __restrict__ q16,
    const __half* __restrict__ k16, const __half* __restrict__ v16,
    __half* __restrict__ o16)
{
    extern __shared__ char asmem[];
    const uint32_t s0 = smem_u32(asmem);
    const uint32_t sQ = s0;                   // 64 rows x 128B = 8KB
    const uint32_t kv0 = s0 + 8192;           // 2 buffers x 32KB: K(16K),V(16K)

    const int tid = threadIdx.x, lane = tid & 31, wid = tid >> 5;  // 4 warps
    const int qt = (gridDim.x - 1) - blockIdx.x;   // 64-row q tile, heavy first
    const int bh = blockIdx.y;
    const int b  = bh >> 4, h = bh & 15;
    const float SCL = 0.125f * 1.4426950408889634f;

    const size_t tokbase = (size_t)b * T_SEQ;
    const size_t headoff = (size_t)h * HD;
    const size_t kvbase  = tokbase * CDIM + headoff;

    const int nkt = (qt >> 1) + 1;   // 128-wide k tiles covering rows <= qt*64+63

    // ---- stage Q (64 rows) + K/V tile 0
    {
        const __half* gq = q16 + (tokbase + qt * 64) * CDIM + headoff;
#pragma unroll
        for (int i = 0; i < 4; ++i) {
            int idx = tid + i * 128;          // 0..511 -> 64 rows x 8 chunks
            int r = idx >> 3, c = idx & 7;
            uint32_t sw = r * 128 + ((c ^ (r & 7)) << 4);
            asm volatile("cp.async.cg.shared.global [%0], [%1], 16;"
                         :: "r"(sQ + sw), "l"(gq + (size_t)r * CDIM + c * 8));
        }
    }
    stage_kv128t(kv0, k16, v16, kvbase, tid);

    uint32_t qf[4][4];
    float o[8][4];
#pragma unroll
    for (int i = 0; i < 8; ++i)
#pragma unroll
        for (int j = 0; j < 4; ++j) o[i][j] = 0.0f;
    float m_[2] = { -1e30f, -1e30f };
    float l_[2] = { 0.0f, 0.0f };

    const int b_rb = (lane & 7) + ((lane >> 4) << 3);
    const int b_kc = (lane >> 3) & 1;
    const int v_rb = (lane & 7) + (((lane >> 3) & 1) << 3);
    const int v_cs = lane >> 4;

    for (int kt = 0; kt < nkt; ++kt) {
        const int cur = kt & 1;
        const uint32_t kvb = kv0 + cur * 32768;
        if (kt + 1 < nkt) {
            stage_kv128t(kv0 + (cur ^ 1) * 32768, k16, v16,
                         kvbase + (size_t)(kt + 1) * 128 * CDIM, tid);
            asm volatile("cp.async.wait_group 1;" ::: "memory");
        } else {
            asm volatile("cp.async.wait_group 0;" ::: "memory");
        }
        __syncthreads();

        if (kt == 0) {   // Q fragments now resident
            const int a_r  = wid * 16 + (lane & 7) + ((lane >> 3) & 1) * 8;
            const int a_kc = lane >> 4;
#pragma unroll
            for (int ks = 0; ks < 4; ++ks) {
                const int ch = ks * 2 + a_kc;
                uint32_t sw = a_r * 128 + ((ch ^ (a_r & 7)) << 4);
                ldsm4(qf[ks][0], qf[ks][1], qf[ks][2], qf[ks][3], sQ + sw);
            }
        }

        const uint32_t sK = kvb, sV = kvb + 16384;

        // ---- S = Q K^T (16 q x 128 k per warp)
        float sc[16][4];
#pragma unroll
        for (int t = 0; t < 16; ++t)
#pragma unroll
            for (int j = 0; j < 4; ++j) sc[t][j] = 0.0f;

#pragma unroll
        for (int ks = 0; ks < 4; ++ks) {
#pragma unroll
            for (int g = 0; g < 8; ++g) {
                const int r = g * 16 + b_rb;
                const int ch = ks * 2 + b_kc;
                uint32_t sw = r * 128 + ((ch ^ (r & 7)) << 4);
                uint32_t k0, k1, k2, k3;
                ldsm4(k0, k1, k2, k3, sK + sw);
                mma_f16(sc[2 * g],     qf[ks], k0, k1);
                mma_f16(sc[2 * g + 1], qf[ks], k2, k3);
            }
        }

        // ---- scale + causal mask (last k-tile only, global indices)
        const bool diag = (kt == nkt - 1);
#pragma unroll
        for (int t = 0; t < 16; ++t)
#pragma unroll
            for (int j = 0; j < 4; ++j) {
                float v = sc[t][j] * SCL;
                if (diag) {
                    const int col = kt * 128 + t * 8 + ((lane & 3) << 1) + (j & 1);
                    const int row = qt * 64 + (wid << 4) + (lane >> 2) + ((j >> 1) << 3);
                    if (col > row) v = -1e30f;
                }
                sc[t][j] = v;
            }

        // ---- online softmax (log2 domain)
#pragma unroll
        for (int hf = 0; hf < 2; ++hf) {
            float mx = -1e30f;
#pragma unroll
            for (int t = 0; t < 16; ++t)
                mx = fmaxf(mx, fmaxf(sc[t][2 * hf], sc[t][2 * hf + 1]));
            mx = fmaxf(mx, __shfl_xor_sync(0xffffffffu, mx, 1));
            mx = fmaxf(mx, __shfl_xor_sync(0xffffffffu, mx, 2));
            const float mn = fmaxf(m_[hf], mx);
            const float corr = ex2f(m_[hf] - mn);
            float rs = 0.0f;
#pragma unroll
            for (int t = 0; t < 16; ++t) {
                float p0 = ex2f(sc[t][2 * hf]     - mn);
                float p1 = ex2f(sc[t][2 * hf + 1] - mn);
                sc[t][2 * hf] = p0; sc[t][2 * hf + 1] = p1;
                rs += p0 + p1;
            }
            rs += __shfl_xor_sync(0xffffffffu, rs, 1);
            rs += __shfl_xor_sync(0xffffffffu, rs, 2);
            l_[hf] = l_[hf] * corr + rs;
            m_[hf] = mn;
#pragma unroll
            for (int nt = 0; nt < 8; ++nt) {
                o[nt][2 * hf]     *= corr;
                o[nt][2 * hf + 1] *= corr;
            }
        }

        // ---- O += P V (P fp16 fragments in registers)
#pragma unroll
        for (int ks2 = 0; ks2 < 8; ++ks2) {
            uint32_t ph[4];
            ph[0] = packh(sc[2 * ks2][0],     sc[2 * ks2][1]);
            ph[1] = packh(sc[2 * ks2][2],     sc[2 * ks2][3]);
            ph[2] = packh(sc[2 * ks2 + 1][0], sc[2 * ks2 + 1][1]);
            ph[3] = packh(sc[2 * ks2 + 1][2], sc[2 * ks2 + 1][3]);
#pragma unroll
            for (int ng = 0; ng < 4; ++ng) {
                const int r = ks2 * 16 + v_rb;
                const int ch = ng * 2 + v_cs;
                uint32_t sw = r * 128 + ((ch ^ (r & 7)) << 4);
                uint32_t v0, v1, v2, v3;
                ldsm4t(v0, v1, v2, v3, sV + sw);
                mma_f16(o[2 * ng],     ph, v0, v1);
                mma_f16(o[2 * ng + 1], ph, v2, v3);
            }
        }
        __syncthreads();
    }

    // ---- epilogue: normalize, store fp16
#pragma unroll
    for (int hf = 0; hf < 2; ++hf) {
        const float inv = 1.0f / l_[hf];
        const int row = qt * 64 + wid * 16 + (lane >> 2) + hf * 8;
        __half* oh = o16 + (tokbase + row) * CDIM + headoff;
#pragma unroll
        for (int nt = 0; nt < 8; ++nt) {
            const int col = nt * 8 + (lane & 3) * 2;
            *(uint32_t*)(oh + col) =
                packh(o[nt][2 * hf] * inv, o[nt][2 * hf + 1] * inv);
        }
    }
}

// ---------------------------------------------------------------------------
// Launch.  Inputs: 0:x 1:mask 2:context_vector 3:w_q 4:w_k 5:w_v 6:w_o 7:b_o
//                  8:context_bias    out: f32 [2,2048,1024]
// ---------------------------------------------------------------------------
extern "C" void kernel_launch(void* const* d_in, const int* in_sizes, int n_in,
                              void* d_out, int out_size)
{
    (void)in_sizes; (void)n_in; (void)out_size;
    const float* x  = (const float*)d_in[0];
    const float* cv = (const float*)d_in[2];
    const float* wq = (const float*)d_in[3];
    const float* wk = (const float*)d_in[4];
    const float* wv = (const float*)d_in[5];
    const float* wo = (const float*)d_in[6];
    const float* bo = (const float*)d_in[7];
    const float* cb = (const float*)d_in[8];
    float* out = (float*)d_out;

    __half *x16, *wq16, *wk16, *wv16, *wo16, *q16, *k16, *v16, *a16;
    cudaGetSymbolAddress((void**)&x16,  g_x16);
    cudaGetSymbolAddress((void**)&wq16, g_wq16);
    cudaGetSymbolAddress((void**)&wk16, g_wk16);
    cudaGetSymbolAddress((void**)&wv16, g_wv16);
    cudaGetSymbolAddress((void**)&wo16, g_wo16);
    cudaGetSymbolAddress((void**)&q16,  g_q16);
    cudaGetSymbolAddress((void**)&k16,  g_k16);
    cudaGetSymbolAddress((void**)&v16,  g_v16);
    cudaGetSymbolAddress((void**)&a16,  g_a16);

    const int gemm_smem = 4 * TILEB;                 // 65536
    cudaFuncSetAttribute(gemm_qkv, cudaFuncAttributeMaxDynamicSharedMemorySize, gemm_smem);
    cudaFuncSetAttribute(gemm_out, cudaFuncAttributeMaxDynamicSharedMemorySize, gemm_smem);
    const int attn_smem = 8192 + 2 * 32768;          // 73728 -> 2 CTAs/SM
    cudaFuncSetAttribute(attn_mma, cudaFuncAttributeMaxDynamicSharedMemorySize, attn_smem);

    const int NX4 = MTOK * CDIM / 4;
    const int NW4 = CDIM * CDIM / 4;

    cvt_all<<<dim3(512, 5), 256>>>(x, wq, wk, wv, wo,
                                   x16, wq16, wk16, wv16, wo16, NW4, NX4);

    gemm_qkv<<<dim3(24, MTOK / 128), 256, gemm_smem>>>(
        x16, wq16, wk16, wv16, q16, k16, v16, cv, cb);

    attn_mma<<<dim3(T_SEQ / 64, NB * NH), 128, attn_smem>>>(
        q16, k16, v16, a16);

    gemm_out<<<dim3(CDIM / 128, MTOK / 128), 256, gemm_smem>>>(
        a16, wo16, out, bo);
}

// round 15
// speedup vs baseline: 1.1142x; 1.0088x over previous
#include <cuda_runtime.h>
#include <cuda_fp16.h>
#include <math.h>
#include <stdint.h>

#define T_SEQ 2048
#define CDIM  1024
#define NB    2
#define NH    16
#define HD    64
#define MTOK  (NB * T_SEQ)   // 4096 token rows

// ---------------------------------------------------------------------------
// Scratch (static device globals)
// ---------------------------------------------------------------------------
__device__ __half g_x16[(size_t)MTOK * CDIM];
__device__ __half g_wq16[(size_t)CDIM * CDIM];
__device__ __half g_wk16[(size_t)CDIM * CDIM];
__device__ __half g_wv16[(size_t)CDIM * CDIM];
__device__ __half g_wo16[(size_t)CDIM * CDIM];
__device__ __half g_q16[(size_t)MTOK * CDIM];
__device__ __half g_k16[(size_t)MTOK * CDIM];
__device__ __half g_v16[(size_t)MTOK * CDIM];
__device__ __half g_a16[(size_t)MTOK * CDIM];

// ---------------------------------------------------------------------------
// Helpers
// ---------------------------------------------------------------------------
__device__ __forceinline__ uint32_t smem_u32(const void* p) {
    uint32_t a;
    asm("{ .reg .u64 t; cvta.to.shared.u64 t, %1; cvt.u32.u64 %0, t; }"
        : "=r"(a) : "l"(p));
    return a;
}
__device__ __forceinline__ float ex2f(float x) {
    float y; asm("ex2.approx.ftz.f32 %0, %1;" : "=f"(y) : "f"(x)); return y;
}
__device__ __forceinline__ void ldsm4(uint32_t& r0, uint32_t& r1,
                                      uint32_t& r2, uint32_t& r3, uint32_t addr) {
    asm volatile("ldmatrix.sync.aligned.m8n8.x4.shared.b16 {%0,%1,%2,%3}, [%4];"
                 : "=r"(r0), "=r"(r1), "=r"(r2), "=r"(r3) : "r"(addr));
}
__device__ __forceinline__ void ldsm4t(uint32_t& r0, uint32_t& r1,
                                       uint32_t& r2, uint32_t& r3, uint32_t addr) {
    asm volatile("ldmatrix.sync.aligned.m8n8.x4.trans.shared.b16 {%0,%1,%2,%3}, [%4];"
                 : "=r"(r0), "=r"(r1), "=r"(r2), "=r"(r3) : "r"(addr));
}
__device__ __forceinline__ void mma_f16(float* c, const uint32_t* a,
                                        uint32_t b0, uint32_t b1) {
    asm volatile(
        "mma.sync.aligned.m16n8k16.row.col.f32.f16.f16.f32 "
        "{%0,%1,%2,%3}, {%4,%5,%6,%7}, {%8,%9}, {%0,%1,%2,%3};"
        : "+f"(c[0]), "+f"(c[1]), "+f"(c[2]), "+f"(c[3])
        : "r"(a[0]), "r"(a[1]), "r"(a[2]), "r"(a[3]), "r"(b0), "r"(b1));
}
__device__ __forceinline__ uint32_t packh(float f0, float f1) {
    __half2 h = __floats2half2_rn(f0, f1);
    return *(uint32_t*)&h;
}

// ---------------------------------------------------------------------------
// fp32 -> fp16 converts: x (grid.y==4) and the 4 weights, one launch
// ---------------------------------------------------------------------------
__global__ __launch_bounds__(256) void cvt_all(
    const float* __restrict__ x,
    const float* __restrict__ w0, const float* __restrict__ w1,
    const float* __restrict__ w2, const float* __restrict__ w3,
    __half* __restrict__ xo,
    __half* __restrict__ o0, __half* __restrict__ o1,
    __half* __restrict__ o2, __half* __restrict__ o3, int nw4, int nx4)
{
    const float* in; __half* out; int n4;
    if (blockIdx.y == 4) { in = x;  out = xo; n4 = nx4; }
    else {
        in  = (blockIdx.y == 0) ? w0 : (blockIdx.y == 1) ? w1 :
              (blockIdx.y == 2) ? w2 : w3;
        out = (blockIdx.y == 0) ? o0 : (blockIdx.y == 1) ? o1 :
              (blockIdx.y == 2) ? o2 : o3;
        n4 = nw4;
    }
    int i = blockIdx.x * blockDim.x + threadIdx.x;
    const int stride = gridDim.x * blockDim.x;
    for (; i < n4; i += stride) {
        float4 v = *(const float4*)(in + (size_t)i * 4);
        uint2 hh; hh.x = packh(v.x, v.y); hh.y = packh(v.z, v.w);
        *(uint2*)(out + (size_t)i * 4) = hh;
    }
}

// ---------------------------------------------------------------------------
// fp16 GEMM core: CTA 64x128, 128 threads (4 warps of 32x64 tile),
// K-tile 64, 2-stage double buffer (48KB smem) -> 3 CTAs/SM.
// ---------------------------------------------------------------------------
#define NT16    16
#define TILEA64 8192      // 64 rows * 128B
#define TILEB128 16384    // 128 rows * 128B
#define GSTAGE  (TILEA64 + TILEB128)   // 24576 per stage

__device__ __forceinline__ void stage_a64(
    uint32_t s, const __half* __restrict__ G, int r0, int koff, int tid)
{
#pragma unroll
    for (int i = 0; i < 4; ++i) {
        int idx = tid + i * 128;          // 0..511 -> 64 rows x 8 chunks
        int r = idx >> 3, c = idx & 7;
        uint32_t sw = r * 128 + ((c ^ (r & 7)) << 4);
        const __half* g = G + (size_t)(r0 + r) * CDIM + koff + c * 8;
        asm volatile("cp.async.cg.shared.global [%0], [%1], 16;"
                     :: "r"(s + sw), "l"(g));
    }
}
__device__ __forceinline__ void stage_b128(
    uint32_t s, const __half* __restrict__ G, int r0, int koff, int tid)
{
#pragma unroll
    for (int i = 0; i < 8; ++i) {
        int idx = tid + i * 128;          // 0..1023 -> 128 rows x 8 chunks
        int r = idx >> 3, c = idx & 7;
        uint32_t sw = r * 128 + ((c ^ (r & 7)) << 4);
        const __half* g = G + (size_t)(r0 + r) * CDIM + koff + c * 8;
        asm volatile("cp.async.cg.shared.global [%0], [%1], 16;"
                     :: "r"(s + sw), "l"(g));
    }
}

__device__ __forceinline__ void gemm_core(
    uint32_t s0, const __half* A16, const __half* B16,
    int m0, int n0, int tid, int lane, int wm, int wn,
    float acc[2][8][4])
{
    uint32_t sA[2] = { s0,           s0 + GSTAGE };
    uint32_t sB[2] = { s0 + TILEA64, s0 + TILEA64 + GSTAGE };

    const int a_r  = wm + (lane & 7) + ((lane >> 3) & 1) * 8;
    const int a_kc = lane >> 4;
    const int b_r  = wn + (lane & 7) + (lane >> 4) * 8;
    const int b_kc = (lane >> 3) & 1;

    stage_a64(sA[0], A16, m0, 0, tid);
    stage_b128(sB[0], B16, n0, 0, tid);
    asm volatile("cp.async.commit_group;" ::: "memory");

    for (int t = 0; t < NT16; ++t) {
        const int cur = t & 1, nxt = cur ^ 1;
        if (t + 1 < NT16) {
            const int ko = (t + 1) * 64;
            stage_a64(sA[nxt], A16, m0, ko, tid);
            stage_b128(sB[nxt], B16, n0, ko, tid);
            asm volatile("cp.async.commit_group;" ::: "memory");
            asm volatile("cp.async.wait_group 1;" ::: "memory");
        } else {
            asm volatile("cp.async.wait_group 0;" ::: "memory");
        }
        __syncthreads();

#pragma unroll
        for (int ks = 0; ks < 4; ++ks) {
            uint32_t af[2][4];
#pragma unroll
            for (int mt = 0; mt < 2; ++mt) {
                const int r = a_r + mt * 16;
                uint32_t off = r * 128 + (((ks * 2 + a_kc) ^ (r & 7)) << 4);
                ldsm4(af[mt][0], af[mt][1], af[mt][2], af[mt][3], sA[cur] + off);
            }
            uint32_t bf[8][2];
#pragma unroll
            for (int p = 0; p < 4; ++p) {
                const int r = b_r + p * 16;
                uint32_t off = r * 128 + (((ks * 2 + b_kc) ^ (r & 7)) << 4);
                ldsm4(bf[2 * p][0], bf[2 * p][1], bf[2 * p + 1][0], bf[2 * p + 1][1],
                      sB[cur] + off);
            }
#pragma unroll
            for (int mt = 0; mt < 2; ++mt)
#pragma unroll
                for (int nt = 0; nt < 8; ++nt)
                    mma_f16(acc[mt][nt], af[mt], bf[nt][0], bf[nt][1]);
        }
        __syncthreads();
    }
}

// Fused QKV projection: grid = (24, 64); 64-row m-tiles; fp16 out.
__global__ __launch_bounds__(128) void gemm_qkv(
    const __half* __restrict__ x16,
    const __half* __restrict__ wq16, const __half* __restrict__ wk16,
    const __half* __restrict__ wv16,
    __half* __restrict__ q16, __half* __restrict__ k16, __half* __restrict__ v16,
    const float* __restrict__ cv, const float* __restrict__ cb)
{
    extern __shared__ char gsm[];
    uint32_t s0 = smem_u32(gsm);

    const int tid = threadIdx.x, lane = tid & 31, wid = tid >> 5;  // 4 warps
    const int wm = (wid >> 1) * 32, wn = (wid & 1) * 64;
    const int wsel = blockIdx.x >> 3;
    const int n0 = (blockIdx.x & 7) * 128;
    const int m0 = blockIdx.y * 64;

    const __half* B16 = (wsel == 0) ? wq16 : (wsel == 1) ? wk16 : wv16;
    __half* O = (wsel == 0) ? q16 : (wsel == 1) ? k16 : v16;

    float acc[2][8][4];
#pragma unroll
    for (int a = 0; a < 2; ++a)
#pragma unroll
        for (int b = 0; b < 8; ++b)
#pragma unroll
            for (int c = 0; c < 4; ++c) acc[a][b][c] = 0.0f;

    gemm_core(s0, x16, B16, m0, n0, tid, lane, wm, wn, acc);

    const int er = lane >> 2, ec = (lane & 3) * 2;
#pragma unroll
    for (int mt = 0; mt < 2; ++mt)
#pragma unroll
        for (int half = 0; half < 2; ++half) {
            const int row = m0 + wm + mt * 16 + er + half * 8;
#pragma unroll
            for (int nt = 0; nt < 8; ++nt) {
                const int col = n0 + wn + nt * 8 + ec;
                float v0 = acc[mt][nt][half * 2 + 0];
                float v1 = acc[mt][nt][half * 2 + 1];
                if (wsel == 0) {
                    const float* cvr = cv + (size_t)row * CDIM;
                    v0 += cb[col]     * cvr[col];
                    v1 += cb[col + 1] * cvr[col + 1];
                }
                *(uint32_t*)(O + (size_t)row * CDIM + col) = packh(v0, v1);
            }
        }
}

// Output projection: grid (8, 64); fp32 out + bias
__global__ __launch_bounds__(128) void gemm_out(
    const __half* __restrict__ a16, const __half* __restrict__ wo16,
    float* __restrict__ Y, const float* __restrict__ bias)
{
    extern __shared__ char gsm[];
    uint32_t s0 = smem_u32(gsm);

    const int tid = threadIdx.x, lane = tid & 31, wid = tid >> 5;
    const int wm = (wid >> 1) * 32, wn = (wid & 1) * 64;
    const int m0 = blockIdx.y * 64, n0 = blockIdx.x * 128;

    float acc[2][8][4];
#pragma unroll
    for (int a = 0; a < 2; ++a)
#pragma unroll
        for (int b = 0; b < 8; ++b)
#pragma unroll
            for (int c = 0; c < 4; ++c) acc[a][b][c] = 0.0f;

    gemm_core(s0, a16, wo16, m0, n0, tid, lane, wm, wn, acc);

    const int er = lane >> 2, ec = (lane & 3) * 2;
#pragma unroll
    for (int mt = 0; mt < 2; ++mt)
#pragma unroll
        for (int half = 0; half < 2; ++half) {
            const int row = m0 + wm + mt * 16 + er + half * 8;
            float* yrow = Y + (size_t)row * CDIM;
#pragma unroll
            for (int nt = 0; nt < 8; ++nt) {
                const int col = n0 + wn + nt * 8 + ec;
                float2 f;
                f.x = acc[mt][nt][half * 2 + 0] + bias[col];
                f.y = acc[mt][nt][half * 2 + 1] + bias[col + 1];
                *(float2*)(yrow + col) = f;
            }
        }
}

// ---------------------------------------------------------------------------
// Causal flash attention (round-14 winner, unchanged): 64 q-rows per CTA,
// 128 threads (4 warps of 16q x 128k), K/V double-buffered, 2 CTAs/SM.
// ---------------------------------------------------------------------------
__device__ __forceinline__ void stage_kv128t(
    uint32_t kvb, const __half* __restrict__ k16, const __half* __restrict__ v16,
    size_t rb, int tid)
{
#pragma unroll
    for (int i = 0; i < 8; ++i) {
        int idx = tid + i * 128;
        int r = idx >> 3, c = idx & 7;
        uint32_t sw = r * 128 + ((c ^ (r & 7)) << 4);
        size_t g = rb + (size_t)r * CDIM + c * 8;
        asm volatile("cp.async.cg.shared.global [%0], [%1], 16;" :: "r"(kvb + sw),         "l"(k16 + g));
        asm volatile("cp.async.cg.shared.global [%0], [%1], 16;" :: "r"(kvb + 16384 + sw), "l"(v16 + g));
    }
    asm volatile("cp.async.commit_group;" ::: "memory");
}

__global__ __launch_bounds__(128) void attn_mma(
    const __half* __restrict__ q16,
    const __half* __restrict__ k16, const __half* __restrict__ v16,
    __half* __restrict__ o16)
{
    extern __shared__ char asmem[];
    const uint32_t s0 = smem_u32(asmem);
    const uint32_t sQ = s0;                   // 64 rows x 128B = 8KB
    const uint32_t kv0 = s0 + 8192;           // 2 buffers x 32KB

    const int tid = threadIdx.x, lane = tid & 31, wid = tid >> 5;
    const int qt = (gridDim.x - 1) - blockIdx.x;
    const int bh = blockIdx.y;
    const int b  = bh >> 4, h = bh & 15;
    const float SCL = 0.125f * 1.4426950408889634f;

    const size_t tokbase = (size_t)b * T_SEQ;
    const size_t headoff = (size_t)h * HD;
    const size_t kvbase  = tokbase * CDIM + headoff;

    const int nkt = (qt >> 1) + 1;

    {
        const __half* gq = q16 + (tokbase + qt * 64) * CDIM + headoff;
#pragma unroll
        for (int i = 0; i < 4; ++i) {
            int idx = tid + i * 128;
            int r = idx >> 3, c = idx & 7;
            uint32_t sw = r * 128 + ((c ^ (r & 7)) << 4);
            asm volatile("cp.async.cg.shared.global [%0], [%1], 16;"
                         :: "r"(sQ + sw), "l"(gq + (size_t)r * CDIM + c * 8));
        }
    }
    stage_kv128t(kv0, k16, v16, kvbase, tid);

    uint32_t qf[4][4];
    float o[8][4];
#pragma unroll
    for (int i = 0; i < 8; ++i)
#pragma unroll
        for (int j = 0; j < 4; ++j) o[i][j] = 0.0f;
    float m_[2] = { -1e30f, -1e30f };
    float l_[2] = { 0.0f, 0.0f };

    const int b_rb = (lane & 7) + ((lane >> 4) << 3);
    const int b_kc = (lane >> 3) & 1;
    const int v_rb = (lane & 7) + (((lane >> 3) & 1) << 3);
    const int v_cs = lane >> 4;

    for (int kt = 0; kt < nkt; ++kt) {
        const int cur = kt & 1;
        const uint32_t kvb = kv0 + cur * 32768;
        if (kt + 1 < nkt) {
            stage_kv128t(kv0 + (cur ^ 1) * 32768, k16, v16,
                         kvbase + (size_t)(kt + 1) * 128 * CDIM, tid);
            asm volatile("cp.async.wait_group 1;" ::: "memory");
        } else {
            asm volatile("cp.async.wait_group 0;" ::: "memory");
        }
        __syncthreads();

        if (kt == 0) {
            const int a_r  = wid * 16 + (lane & 7) + ((lane >> 3) & 1) * 8;
            const int a_kc = lane >> 4;
#pragma unroll
            for (int ks = 0; ks < 4; ++ks) {
                const int ch = ks * 2 + a_kc;
                uint32_t sw = a_r * 128 + ((ch ^ (a_r & 7)) << 4);
                ldsm4(qf[ks][0], qf[ks][1], qf[ks][2], qf[ks][3], sQ + sw);
            }
        }

        const uint32_t sK = kvb, sV = kvb + 16384;

        float sc[16][4];
#pragma unroll
        for (int t = 0; t < 16; ++t)
#pragma unroll
            for (int j = 0; j < 4; ++j) sc[t][j] = 0.0f;

#pragma unroll
        for (int ks = 0; ks < 4; ++ks) {
#pragma unroll
            for (int g = 0; g < 8; ++g) {
                const int r = g * 16 + b_rb;
                const int ch = ks * 2 + b_kc;
                uint32_t sw = r * 128 + ((ch ^ (r & 7)) << 4);
                uint32_t k0, k1, k2, k3;
                ldsm4(k0, k1, k2, k3, sK + sw);
                mma_f16(sc[2 * g],     qf[ks], k0, k1);
                mma_f16(sc[2 * g + 1], qf[ks], k2, k3);
            }
        }

        const bool diag = (kt == nkt - 1);
#pragma unroll
        for (int t = 0; t < 16; ++t)
#pragma unroll
            for (int j = 0; j < 4; ++j) {
                float v = sc[t][j] * SCL;
                if (diag) {
                    const int col = kt * 128 + t * 8 + ((lane & 3) << 1) + (j & 1);
                    const int row = qt * 64 + (wid << 4) + (lane >> 2) + ((j >> 1) << 3);
                    if (col > row) v = -1e30f;
                }
                sc[t][j] = v;
            }

#pragma unroll
        for (int hf = 0; hf < 2; ++hf) {
            float mx = -1e30f;
#pragma unroll
            for (int t = 0; t < 16; ++t)
                mx = fmaxf(mx, fmaxf(sc[t][2 * hf], sc[t][2 * hf + 1]));
            mx = fmaxf(mx, __shfl_xor_sync(0xffffffffu, mx, 1));
            mx = fmaxf(mx, __shfl_xor_sync(0xffffffffu, mx, 2));
            const float mn = fmaxf(m_[hf], mx);
            const float corr = ex2f(m_[hf] - mn);
            float rs = 0.0f;
#pragma unroll
            for (int t = 0; t < 16; ++t) {
                float p0 = ex2f(sc[t][2 * hf]     - mn);
                float p1 = ex2f(sc[t][2 * hf + 1] - mn);
                sc[t][2 * hf] = p0; sc[t][2 * hf + 1] = p1;
                rs += p0 + p1;
            }
            rs += __shfl_xor_sync(0xffffffffu, rs, 1);
            rs += __shfl_xor_sync(0xffffffffu, rs, 2);
            l_[hf] = l_[hf] * corr + rs;
            m_[hf] = mn;
#pragma unroll
            for (int nt = 0; nt < 8; ++nt) {
                o[nt][2 * hf]     *= corr;
                o[nt][2 * hf + 1] *= corr;
            }
        }

#pragma unroll
        for (int ks2 = 0; ks2 < 8; ++ks2) {
            uint32_t ph[4];
            ph[0] = packh(sc[2 * ks2][0],     sc[2 * ks2][1]);
            ph[1] = packh(sc[2 * ks2][2],     sc[2 * ks2][3]);
            ph[2] = packh(sc[2 * ks2 + 1][0], sc[2 * ks2 + 1][1]);
            ph[3] = packh(sc[2 * ks2 + 1][2], sc[2 * ks2 + 1][3]);
#pragma unroll
            for (int ng = 0; ng < 4; ++ng) {
                const int r = ks2 * 16 + v_rb;
                const int ch = ng * 2 + v_cs;
                uint32_t sw = r * 128 + ((ch ^ (r & 7)) << 4);
                uint32_t v0, v1, v2, v3;
                ldsm4t(v0, v1, v2, v3, sV + sw);
                mma_f16(o[2 * ng],     ph, v0, v1);
                mma_f16(o[2 * ng + 1], ph, v2, v3);
            }
        }
        __syncthreads();
    }

#pragma unroll
    for (int hf = 0; hf < 2; ++hf) {
        const float inv = 1.0f / l_[hf];
        const int row = qt * 64 + wid * 16 + (lane >> 2) + hf * 8;
        __half* oh = o16 + (tokbase + row) * CDIM + headoff;
#pragma unroll
        for (int nt = 0; nt < 8; ++nt) {
            const int col = nt * 8 + (lane & 3) * 2;
            *(uint32_t*)(oh + col) =
                packh(o[nt][2 * hf] * inv, o[nt][2 * hf + 1] * inv);
        }
    }
}

// ---------------------------------------------------------------------------
// Launch.  Inputs: 0:x 1:mask 2:context_vector 3:w_q 4:w_k 5:w_v 6:w_o 7:b_o
//                  8:context_bias    out: f32 [2,2048,1024]
// ---------------------------------------------------------------------------
extern "C" void kernel_launch(void* const* d_in, const int* in_sizes, int n_in,
                              void* d_out, int out_size)
{
    (void)in_sizes; (void)n_in; (void)out_size;
    const float* x  = (const float*)d_in[0];
    const float* cv = (const float*)d_in[2];
    const float* wq = (const float*)d_in[3];
    const float* wk = (const float*)d_in[4];
    const float* wv = (const float*)d_in[5];
    const float* wo = (const float*)d_in[6];
    const float* bo = (const float*)d_in[7];
    const float* cb = (const float*)d_in[8];
    float* out = (float*)d_out;

    __half *x16, *wq16, *wk16, *wv16, *wo16, *q16, *k16, *v16, *a16;
    cudaGetSymbolAddress((void**)&x16,  g_x16);
    cudaGetSymbolAddress((void**)&wq16, g_wq16);
    cudaGetSymbolAddress((void**)&wk16, g_wk16);
    cudaGetSymbolAddress((void**)&wv16, g_wv16);
    cudaGetSymbolAddress((void**)&wo16, g_wo16);
    cudaGetSymbolAddress((void**)&q16,  g_q16);
    cudaGetSymbolAddress((void**)&k16,  g_k16);
    cudaGetSymbolAddress((void**)&v16,  g_v16);
    cudaGetSymbolAddress((void**)&a16,  g_a16);

    const int gemm_smem = 2 * GSTAGE;                // 49152 -> 3 CTAs/SM (regs)
    cudaFuncSetAttribute(gemm_qkv, cudaFuncAttributeMaxDynamicSharedMemorySize, gemm_smem);
    cudaFuncSetAttribute(gemm_out, cudaFuncAttributeMaxDynamicSharedMemorySize, gemm_smem);
    const int attn_smem = 8192 + 2 * 32768;          // 73728 -> 2 CTAs/SM
    cudaFuncSetAttribute(attn_mma, cudaFuncAttributeMaxDynamicSharedMemorySize, attn_smem);

    const int NX4 = MTOK * CDIM / 4;
    const int NW4 = CDIM * CDIM / 4;

    cvt_all<<<dim3(512, 5), 256>>>(x, wq, wk, wv, wo,
                                   x16, wq16, wk16, wv16, wo16, NW4, NX4);

    gemm_qkv<<<dim3(24, MTOK / 64), 128, gemm_smem>>>(
        x16, wq16, wk16, wv16, q16, k16, v16, cv, cb);

    attn_mma<<<dim3(T_SEQ / 64, NB * NH), 128, attn_smem>>>(
        q16, k16, v16, a16);

    gemm_out<<<dim3(CDIM / 128, MTOK / 64), 128, gemm_smem>>>(
        a16, wo16, out, bo);
}